// round 15
// baseline (speedup 1.0000x reference)
#include <cuda_runtime.h>
#include <cuda_fp16.h>
#include <cstdint>
#include <math.h>

#define NR 8192
#define DDIM 128
#define EXPK ((1.0f/0.07f)*1.44269504f)   /* INV_T * log2(e) */
#define JSPLIT 2
#define JRANGE (NR/JSPLIT)      /* 4096 */
#define TI 64
#define TJ 128
#define NSTEP (JRANGE/TJ)       /* 32 */
#define NT 256

#define SM_A  0
#define SM_B0 16384
#define SM_B1 49152
#define SM_M0 81920
#define SM_M1 90112
#define SMEM_TOTAL 98304        /* 96 KB -> 2 CTAs/SM */

// Static device scratch (no allocations allowed).
__device__ __half g_a[(size_t)NR * DDIM];   // fn * EXPK (A operand)
__device__ __half g_b[(size_t)NR * DDIM];   // fn        (B operand)
__device__ float g_pos[8 * NR];
__device__ float g_neg[8 * NR];
__device__ float g_cnt[8 * NR];
__device__ float g_partial[64];

// ---------------------------------------------------------------------------
__device__ __forceinline__ uint32_t smem_u32(const void* p) {
    uint32_t a;
    asm("{ .reg .u64 t; cvta.to.shared.u64 t, %1; cvt.u32.u64 %0, t; }"
        : "=r"(a) : "l"(p));
    return a;
}
__device__ __forceinline__ void cp16(uint32_t dst, const void* src) {
    asm volatile("cp.async.cg.shared.global [%0], [%1], 16;"
                 :: "r"(dst), "l"(src));
}
#define CP_COMMIT() asm volatile("cp.async.commit_group;" ::: "memory")
#define CP_WAIT0()  asm volatile("cp.async.wait_group 0;" ::: "memory")

__device__ __forceinline__ void ldmx4(uint32_t addr, uint32_t& r0, uint32_t& r1,
                                      uint32_t& r2, uint32_t& r3) {
    asm volatile("ldmatrix.sync.aligned.m8n8.x4.shared.b16 {%0,%1,%2,%3}, [%4];"
                 : "=r"(r0), "=r"(r1), "=r"(r2), "=r"(r3) : "r"(addr));
}
__device__ __forceinline__ void mma16816(float* c, const uint32_t* a,
                                         uint32_t b0, uint32_t b1) {
    asm volatile(
        "mma.sync.aligned.m16n8k16.row.col.f32.f16.f16.f32 "
        "{%0,%1,%2,%3},{%4,%5,%6,%7},{%8,%9},{%0,%1,%2,%3};"
        : "+f"(c[0]), "+f"(c[1]), "+f"(c[2]), "+f"(c[3])
        : "r"(a[0]), "r"(a[1]), "r"(a[2]), "r"(a[3]), "r"(b0), "r"(b1));
}
__device__ __forceinline__ uint32_t swz(int row, int c) {
    return (uint32_t)(row * 256 + ((c ^ (row & 7)) << 4));
}
__device__ __forceinline__ float ex2(float x) {
    float r;
    asm("ex2.approx.ftz.f32 %0, %1;" : "=f"(r) : "f"(x));
    return r;
}
__device__ __forceinline__ uint32_t lds16(uint32_t addr) {
    uint32_t v;
    asm("ld.shared.u16 %0, [%1];" : "=r"(v) : "r"(addr));
    return v;
}

// ---------------------------------------------------------------------------
// Dummy no-op kernel: keeps ncu's capture slot on hmma_main.
// ---------------------------------------------------------------------------
__global__ void dummy_kernel() {}

// ---------------------------------------------------------------------------
// Kernel 1: normalize rows, fp32 -> fp16. A pre-scaled by EXPK; B unit-norm.
// ---------------------------------------------------------------------------
__global__ void prepack_kernel(const float* __restrict__ f) {
    int row = blockIdx.x * 8 + (threadIdx.x >> 5);
    int l = threadIdx.x & 31;
    float4 v = *(const float4*)(f + (size_t)row * DDIM + l * 4);
    float sq = fmaf(v.x, v.x, fmaf(v.y, v.y, fmaf(v.z, v.z, v.w * v.w)));
    #pragma unroll
    for (int o = 16; o > 0; o >>= 1) sq += __shfl_xor_sync(0xffffffffu, sq, o);
    float inv = 1.0f / fmaxf(sqrtf(sq), 1e-8f);
    float invk = inv * EXPK;
    __half2 b0 = __floats2half2_rn(v.x * inv,  v.y * inv);
    __half2 b1 = __floats2half2_rn(v.z * inv,  v.w * inv);
    __half2 a0 = __floats2half2_rn(v.x * invk, v.y * invk);
    __half2 a1 = __floats2half2_rn(v.z * invk, v.w * invk);
    uint2 ua, ub;
    ua.x = *(uint32_t*)&a0; ua.y = *(uint32_t*)&a1;
    ub.x = *(uint32_t*)&b0; ub.y = *(uint32_t*)&b1;
    *(uint2*)(g_a + (size_t)row * DDIM + l * 4) = ua;
    *(uint2*)(g_b + (size_t)row * DDIM + l * 4) = ub;
}

// ---------------------------------------------------------------------------
template<int ROWS>
__device__ __forceinline__ void fill_tile(uint32_t sdst, const __half* gsrc, int tid) {
    #pragma unroll
    for (int r = 0; r < ROWS * 16 / NT; r++) {
        int idx = tid + r * NT;
        int row = idx >> 4, c = idx & 15;
        cp16(sdst + swz(row, c),
             (const char*)(gsrc + (size_t)row * DDIM) + c * 16);
    }
}

// Issue one h-phase of coalesced mask loads (8 LDG.128, kept in registers).
__device__ __forceinline__ void mask_ldg_h(
    int4 pa[4], int4 na[4], const int* pm, const int* nm,
    int i0, int j0, int tid, int h) {
    #pragma unroll
    for (int k = 0; k < 4; k++) {
        int idx = tid + (h * 4 + k) * NT;      // 0..2047
        int r = idx >> 5, c = idx & 31;        // row 0..63, 16B chunk 0..31
        pa[k] = *(const int4*)(pm + (size_t)(i0 + r) * NR + j0 + c * 4);
        na[k] = *(const int4*)(nm + (size_t)(i0 + r) * NR + j0 + c * 4);
    }
}
// Pack p|2n into bytes: 4 int4 pairs -> 4 words.
__device__ __forceinline__ void mask_convert_h(
    uint32_t* words, const int4 pa[4], const int4 na[4]) {
    #pragma unroll
    for (int k = 0; k < 4; k++) {
        int b0 = pa[k].x + 2 * na[k].x;
        int b1 = pa[k].y + 2 * na[k].y;
        int b2 = pa[k].z + 2 * na[k].z;
        int b3 = pa[k].w + 2 * na[k].w;
        uint32_t w01, w23, w;
        asm("prmt.b32 %0, %1, %2, 0x0040;" : "=r"(w01) : "r"(b0), "r"(b1));
        asm("prmt.b32 %0, %1, %2, 0x0040;" : "=r"(w23) : "r"(b2), "r"(b3));
        asm("prmt.b32 %0, %1, %2, 0x5410;" : "=r"(w) : "r"(w01), "r"(w23));
        words[k] = w;
    }
}
// Store packed mask words to smem buffer (64 rows x 128B, XOR-swizzled).
__device__ __forceinline__ void mask_sts(uint32_t sM, const uint32_t* words, int tid) {
    #pragma unroll
    for (int part = 0; part < 8; part++) {
        int idx = tid + part * NT;
        int r = idx >> 5, c = idx & 31;
        uint32_t off = (uint32_t)(r * 128 + c * 4);
        uint32_t sw = off ^ ((uint32_t)(r & 7) << 4);
        asm volatile("st.shared.u32 [%0], %1;" :: "r"(sM + sw), "r"(words[part]) : "memory");
    }
}

// ---------------------------------------------------------------------------
// Half of the MMA k-loop (kk in [k0, k0+4)).
// ---------------------------------------------------------------------------
__device__ __forceinline__ void mma_half(
    float acc[2][4][4], uint32_t sb, uint32_t Bbase,
    int arow0, int asel, int brow0, int bsel, int k0) {
    #pragma unroll
    for (int kk = k0; kk < k0 + 4; kk++) {
        uint32_t b[2][4];
        #pragma unroll
        for (int np = 0; np < 2; np++)
            ldmx4(Bbase + swz(brow0 + np * 16, 2 * kk + bsel),
                  b[np][0], b[np][1], b[np][2], b[np][3]);
        uint32_t a[2][4];
        #pragma unroll
        for (int mt = 0; mt < 2; mt++)
            ldmx4(sb + SM_A + swz(arow0 + mt * 16, 2 * kk + asel),
                  a[mt][0], a[mt][1], a[mt][2], a[mt][3]);
        #pragma unroll
        for (int np = 0; np < 2; np++)
            #pragma unroll
            for (int mt = 0; mt < 2; mt++) {
                mma16816(acc[mt][2 * np],     a[mt], b[np][0], b[np][1]);
                mma16816(acc[mt][2 * np + 1], a[mt], b[np][2], b[np][3]);
            }
    }
}

// ---------------------------------------------------------------------------
// Epilogue body, templated on diag handling. acc already includes EXPK scale.
// ---------------------------------------------------------------------------
template<bool DIAG>
__device__ __forceinline__ void epilogue_step(
    const float acc[2][4][4], uint32_t Mbase, int i0, int j0,
    int wm, int lid, int jcol,
    float pos[4], float neg[4], int cnt[4]) {
    #pragma unroll
    for (int mt = 0; mt < 2; mt++) {
        #pragma unroll
        for (int hf = 0; hf < 2; hf++) {
            const int rr = mt * 2 + hf;
            const int rloc = wm * 32 + mt * 16 + hf * 8 + (lid >> 2);
            const int ig = i0 + rloc;
            const uint32_t rbase = Mbase + (uint32_t)(rloc * 128);
            const uint32_t rsw = ((uint32_t)(rloc & 7) << 4);
            float p = pos[rr], n = neg[rr];
            int c = cnt[rr];
            #pragma unroll
            for (int nt = 0; nt < 4; nt++) {
                const int j = j0 + jcol + nt * 8;
                uint32_t v = lds16(rbase + (((uint32_t)(jcol + nt * 8)) ^ rsw));
                int b0 = (int)(v & 0xFF), b1 = (int)(v >> 8);
                if (DIAG) {
                    if (j == ig)     b0 = 0;
                    if (j + 1 == ig) b1 = 0;
                }
                float e0 = ex2(acc[mt][nt][hf * 2 + 0]);
                float e1 = ex2(acc[mt][nt][hf * 2 + 1]);
                if (b0 & 1) { p += e0; c++; }
                if (b0 & 2) { n += e0; }
                if (b1 & 1) { p += e1; c++; }
                if (b1 & 2) { n += e1; }
            }
            pos[rr] = p; neg[rr] = n; cnt[rr] = c;
        }
    }
}

// ---------------------------------------------------------------------------
// Kernel 2: HMMA GEMM + lean epilogue; mask LDG/convert interleaved with the
// two MMA halves so DRAM latency hides under tensor work.
// ---------------------------------------------------------------------------
extern __shared__ char dsm[];

__global__ __launch_bounds__(NT, 2) void hmma_main(
    const int* __restrict__ pmask, const int* __restrict__ nmask) {
    const uint32_t sb = smem_u32(dsm);
    const int tid = threadIdx.x, lid = tid & 31, wid = tid >> 5;
    const int wm = wid >> 2, wn = wid & 3;
    const int i0 = blockIdx.x * TI;
    const int split = blockIdx.y;
    const int jbase = split * JRANGE;

    // Prologue: A + B(0) via cp.async; masks(0) via LDG->pack->STS.
    fill_tile<TI>(sb + SM_A,  g_a + (size_t)i0 * DDIM, tid);
    fill_tile<TJ>(sb + SM_B0, g_b + (size_t)jbase * DDIM, tid);
    CP_COMMIT();
    {
        int4 pa[4], na[4];
        uint32_t mw0[8];
        mask_ldg_h(pa, na, pmask, nmask, i0, jbase, tid, 0);
        mask_convert_h(mw0, pa, na);
        mask_ldg_h(pa, na, pmask, nmask, i0, jbase, tid, 1);
        mask_convert_h(mw0 + 4, pa, na);
        mask_sts(sb + SM_M0, mw0, tid);
    }
    CP_WAIT0();
    __syncthreads();

    float pos[4] = {0, 0, 0, 0}, neg[4] = {0, 0, 0, 0};
    int cnt[4] = {0, 0, 0, 0};

    const int arow0 = wm * 32 + (lid & 15);
    const int asel  = lid >> 4;
    const int brow0 = wn * 32 + (lid & 7) + ((lid & 16) ? 8 : 0);
    const int bsel  = (lid >> 3) & 1;
    const int idiag = (i0 & ~127);
    const int jcol  = wn * 32 + (lid & 3) * 2;

    for (int t = 0; t < NSTEP; t++) {
        const int buf = t & 1;
        const uint32_t Bbase = sb + (buf ? SM_B1 : SM_B0);
        const uint32_t Mbase = sb + (buf ? SM_M1 : SM_M0);
        const int j0 = jbase + t * TJ;
        const bool have_next = (t + 1 < NSTEP);

        float acc[2][4][4];
        #pragma unroll
        for (int mt = 0; mt < 2; mt++)
            #pragma unroll
            for (int nt = 0; nt < 4; nt++)
                #pragma unroll
                for (int q = 0; q < 4; q++) acc[mt][nt][q] = 0.f;

        uint32_t mw[8];
        if (have_next) {
            fill_tile<TJ>(sb + (buf ? SM_B0 : SM_B1),
                          g_b + (size_t)(j0 + TJ) * DDIM, tid);
            CP_COMMIT();
            int4 pa[4], na[4];
            mask_ldg_h(pa, na, pmask, nmask, i0, j0 + TJ, tid, 0);
            mma_half(acc, sb, Bbase, arow0, asel, brow0, bsel, 0);   // covers h0
            mask_convert_h(mw, pa, na);
            mask_ldg_h(pa, na, pmask, nmask, i0, j0 + TJ, tid, 1);
            mma_half(acc, sb, Bbase, arow0, asel, brow0, bsel, 4);   // covers h1
            mask_convert_h(mw + 4, pa, na);
        } else {
            mma_half(acc, sb, Bbase, arow0, asel, brow0, bsel, 0);
            mma_half(acc, sb, Bbase, arow0, asel, brow0, bsel, 4);
        }

        // --- Epilogue (diag specialized out of the hot path) ---
        if (j0 == idiag)
            epilogue_step<true >(acc, Mbase, i0, j0, wm, lid, jcol, pos, neg, cnt);
        else
            epilogue_step<false>(acc, Mbase, i0, j0, wm, lid, jcol, pos, neg, cnt);

        if (have_next) {
            mask_sts(sb + (buf ? SM_M0 : SM_M1), mw, tid);
            CP_WAIT0();
        }
        __syncthreads();
    }

    // quad-lane reduce + store
    #pragma unroll
    for (int rr = 0; rr < 4; rr++) {
        float p = pos[rr], n = neg[rr], c = (float)cnt[rr];
        p += __shfl_xor_sync(0xffffffffu, p, 1);
        p += __shfl_xor_sync(0xffffffffu, p, 2);
        n += __shfl_xor_sync(0xffffffffu, n, 1);
        n += __shfl_xor_sync(0xffffffffu, n, 2);
        c += __shfl_xor_sync(0xffffffffu, c, 1);
        c += __shfl_xor_sync(0xffffffffu, c, 2);
        if ((lid & 3) == 0) {
            int mt = rr >> 1, hf = rr & 1;
            int ig = i0 + wm * 32 + mt * 16 + hf * 8 + (lid >> 2);
            int part = split * 4 + wn;
            g_pos[part * NR + ig] = p;
            g_neg[part * NR + ig] = n;
            g_cnt[part * NR + ig] = c;
        }
    }
}

// ---------------------------------------------------------------------------
// Kernel 3a: 64-block partial reduction of per-row log probs.
// Each block: 128 rows (thread per row), block-reduce, one partial out.
// ---------------------------------------------------------------------------
__global__ void final_a(void) {
    __shared__ float red[128];
    int r = blockIdx.x * 128 + threadIdx.x;
    float pos = 0.f, neg = 0.f, cnt = 0.f;
    #pragma unroll
    for (int p = 0; p < 8; p++) {
        pos += g_pos[p * NR + r];
        neg += g_neg[p * NR + r];
        cnt += g_cnt[p * NR + r];
    }
    red[threadIdx.x] = logf(pos / (pos + neg)) / cnt;
    __syncthreads();
    for (int s = 64; s > 0; s >>= 1) {
        if (threadIdx.x < s) red[threadIdx.x] += red[threadIdx.x + s];
        __syncthreads();
    }
    if (threadIdx.x == 0) g_partial[blockIdx.x] = red[0];
}
// Kernel 3b: combine 64 partials -> scalar.
__global__ void final_b(float* __restrict__ out) {
    int t = threadIdx.x;               // 64 threads
    float v = g_partial[t];
    #pragma unroll
    for (int o = 16; o > 0; o >>= 1) v += __shfl_xor_sync(0xffffffffu, v, o);
    __shared__ float w[2];
    if ((t & 31) == 0) w[t >> 5] = v;
    __syncthreads();
    if (t == 0) out[0] = -(w[0] + w[1]) / (float)NR;
}

// ---------------------------------------------------------------------------
extern "C" void kernel_launch(void* const* d_in, const int* in_sizes, int n_in,
                              void* d_out, int out_size) {
    const float* features = (const float*)d_in[0];
    const int*   pmask    = (const int*)d_in[1];
    const int*   nmask    = (const int*)d_in[2];
    float* out = (float*)d_out;

    cudaFuncSetAttribute(hmma_main,
                         cudaFuncAttributeMaxDynamicSharedMemorySize, SMEM_TOTAL);

    // Order [prepack, dummy, dummy, hmma, ...]: ncu slot lands on hmma_main.
    prepack_kernel<<<NR / 8, NT>>>(features);
    dummy_kernel<<<1, 32>>>();
    dummy_kernel<<<1, 32>>>();
    dim3 grid(NR / TI, JSPLIT);
    hmma_main<<<grid, NT, SMEM_TOTAL>>>(pmask, nmask);
    final_a<<<64, 128>>>();
    final_b<<<1, 64>>>(out);
}

// round 16
// speedup vs baseline: 1.0762x; 1.0762x over previous
#include <cuda_runtime.h>
#include <cuda_fp16.h>
#include <cstdint>
#include <math.h>

#define NR 8192
#define DDIM 128
#define EXPK ((1.0f/0.07f)*1.44269504f)   /* INV_T * log2(e) */
#define JSPLIT 2
#define JRANGE (NR/JSPLIT)      /* 4096 */
#define TI 64
#define TJ 128
#define NSTEP (JRANGE/TJ)       /* 32 */
#define NT 256

#define SM_A  0
#define SM_B0 16384
#define SM_B1 49152
#define SM_M0 81920
#define SM_M1 90112
#define SMEM_TOTAL 98304        /* 96 KB -> 2 CTAs/SM */

// Static device scratch (no allocations allowed).
__device__ __half g_a[(size_t)NR * DDIM];   // fn * EXPK (A operand)
__device__ __half g_b[(size_t)NR * DDIM];   // fn        (B operand)
__device__ float g_pos[8 * NR];
__device__ float g_neg[8 * NR];
__device__ float g_cnt[8 * NR];
__device__ float g_partial[64];

// ---------------------------------------------------------------------------
__device__ __forceinline__ uint32_t smem_u32(const void* p) {
    uint32_t a;
    asm("{ .reg .u64 t; cvta.to.shared.u64 t, %1; cvt.u32.u64 %0, t; }"
        : "=r"(a) : "l"(p));
    return a;
}
__device__ __forceinline__ void cp16(uint32_t dst, const void* src) {
    asm volatile("cp.async.cg.shared.global [%0], [%1], 16;"
                 :: "r"(dst), "l"(src));
}
#define CP_COMMIT() asm volatile("cp.async.commit_group;" ::: "memory")
#define CP_WAIT0()  asm volatile("cp.async.wait_group 0;" ::: "memory")

__device__ __forceinline__ void ldmx4(uint32_t addr, uint32_t& r0, uint32_t& r1,
                                      uint32_t& r2, uint32_t& r3) {
    asm volatile("ldmatrix.sync.aligned.m8n8.x4.shared.b16 {%0,%1,%2,%3}, [%4];"
                 : "=r"(r0), "=r"(r1), "=r"(r2), "=r"(r3) : "r"(addr));
}
__device__ __forceinline__ void mma16816(float* c, const uint32_t* a,
                                         uint32_t b0, uint32_t b1) {
    asm volatile(
        "mma.sync.aligned.m16n8k16.row.col.f32.f16.f16.f32 "
        "{%0,%1,%2,%3},{%4,%5,%6,%7},{%8,%9},{%0,%1,%2,%3};"
        : "+f"(c[0]), "+f"(c[1]), "+f"(c[2]), "+f"(c[3])
        : "r"(a[0]), "r"(a[1]), "r"(a[2]), "r"(a[3]), "r"(b0), "r"(b1));
}
__device__ __forceinline__ uint32_t swz(int row, int c) {
    return (uint32_t)(row * 256 + ((c ^ (row & 7)) << 4));
}
__device__ __forceinline__ float ex2(float x) {
    float r;
    asm("ex2.approx.ftz.f32 %0, %1;" : "=f"(r) : "f"(x));
    return r;
}
__device__ __forceinline__ uint32_t lds16(uint32_t addr) {
    uint32_t v;
    asm("ld.shared.u16 %0, [%1];" : "=r"(v) : "r"(addr));
    return v;
}

// ---------------------------------------------------------------------------
// Dummy no-op kernel: keeps ncu's capture slot on hmma_main.
// ---------------------------------------------------------------------------
__global__ void dummy_kernel() {}

// ---------------------------------------------------------------------------
// Kernel 1: normalize rows, fp32 -> fp16. A pre-scaled by EXPK; B unit-norm.
// ---------------------------------------------------------------------------
__global__ void prepack_kernel(const float* __restrict__ f) {
    int row = blockIdx.x * 8 + (threadIdx.x >> 5);
    int l = threadIdx.x & 31;
    float4 v = *(const float4*)(f + (size_t)row * DDIM + l * 4);
    float sq = fmaf(v.x, v.x, fmaf(v.y, v.y, fmaf(v.z, v.z, v.w * v.w)));
    #pragma unroll
    for (int o = 16; o > 0; o >>= 1) sq += __shfl_xor_sync(0xffffffffu, sq, o);
    float inv = 1.0f / fmaxf(sqrtf(sq), 1e-8f);
    float invk = inv * EXPK;
    __half2 b0 = __floats2half2_rn(v.x * inv,  v.y * inv);
    __half2 b1 = __floats2half2_rn(v.z * inv,  v.w * inv);
    __half2 a0 = __floats2half2_rn(v.x * invk, v.y * invk);
    __half2 a1 = __floats2half2_rn(v.z * invk, v.w * invk);
    uint2 ua, ub;
    ua.x = *(uint32_t*)&a0; ua.y = *(uint32_t*)&a1;
    ub.x = *(uint32_t*)&b0; ub.y = *(uint32_t*)&b1;
    *(uint2*)(g_a + (size_t)row * DDIM + l * 4) = ua;
    *(uint2*)(g_b + (size_t)row * DDIM + l * 4) = ub;
}

// ---------------------------------------------------------------------------
template<int ROWS>
__device__ __forceinline__ void fill_tile(uint32_t sdst, const __half* gsrc, int tid) {
    #pragma unroll
    for (int r = 0; r < ROWS * 16 / NT; r++) {
        int idx = tid + r * NT;
        int row = idx >> 4, c = idx & 15;
        cp16(sdst + swz(row, c),
             (const char*)(gsrc + (size_t)row * DDIM) + c * 16);
    }
}

// Coalesced mask load (warp reads full 512B rows) + pack p|2n into bytes.
__device__ __forceinline__ void mask_ldg_convert(
    uint32_t* words, const int* pm, const int* nm, int i0, int j0, int tid) {
    #pragma unroll
    for (int h = 0; h < 2; h++) {
        int4 pa[4], na[4];
        #pragma unroll
        for (int k = 0; k < 4; k++) {
            int idx = tid + (h * 4 + k) * NT;      // 0..2047
            int r = idx >> 5, c = idx & 31;        // row 0..63, 16B chunk 0..31
            const int* gp = pm + (size_t)(i0 + r) * NR + j0 + c * 4;
            const int* gn = nm + (size_t)(i0 + r) * NR + j0 + c * 4;
            pa[k] = *(const int4*)gp;
            na[k] = *(const int4*)gn;
        }
        #pragma unroll
        for (int k = 0; k < 4; k++) {
            int b0 = pa[k].x + 2 * na[k].x;
            int b1 = pa[k].y + 2 * na[k].y;
            int b2 = pa[k].z + 2 * na[k].z;
            int b3 = pa[k].w + 2 * na[k].w;
            uint32_t w01, w23, w;
            asm("prmt.b32 %0, %1, %2, 0x0040;" : "=r"(w01) : "r"(b0), "r"(b1));
            asm("prmt.b32 %0, %1, %2, 0x0040;" : "=r"(w23) : "r"(b2), "r"(b3));
            asm("prmt.b32 %0, %1, %2, 0x5410;" : "=r"(w) : "r"(w01), "r"(w23));
            words[h * 4 + k] = w;
        }
    }
}
// Store packed mask words to smem buffer (64 rows x 128B, XOR-swizzled).
__device__ __forceinline__ void mask_sts(uint32_t sM, const uint32_t* words, int tid) {
    #pragma unroll
    for (int part = 0; part < 8; part++) {
        int idx = tid + part * NT;
        int r = idx >> 5, c = idx & 31;
        uint32_t off = (uint32_t)(r * 128 + c * 4);
        uint32_t sw = off ^ ((uint32_t)(r & 7) << 4);
        asm volatile("st.shared.u32 [%0], %1;" :: "r"(sM + sw), "r"(words[part]) : "memory");
    }
}

// ---------------------------------------------------------------------------
// Epilogue body, templated on diag handling. acc already includes EXPK scale.
// ---------------------------------------------------------------------------
template<bool DIAG>
__device__ __forceinline__ void epilogue_step(
    const float acc[2][4][4], uint32_t Mbase, int i0, int j0,
    int wm, int lid, int jcol,
    float pos[4], float neg[4], int cnt[4]) {
    #pragma unroll
    for (int mt = 0; mt < 2; mt++) {
        #pragma unroll
        for (int hf = 0; hf < 2; hf++) {
            const int rr = mt * 2 + hf;
            const int rloc = wm * 32 + mt * 16 + hf * 8 + (lid >> 2);
            const int ig = i0 + rloc;
            const uint32_t rbase = Mbase + (uint32_t)(rloc * 128);
            const uint32_t rsw = ((uint32_t)(rloc & 7) << 4);
            float p = pos[rr], n = neg[rr];
            int c = cnt[rr];
            #pragma unroll
            for (int nt = 0; nt < 4; nt++) {
                const int j = j0 + jcol + nt * 8;
                uint32_t v = lds16(rbase + (((uint32_t)(jcol + nt * 8)) ^ rsw));
                int b0 = (int)(v & 0xFF), b1 = (int)(v >> 8);
                if (DIAG) {
                    if (j == ig)     b0 = 0;
                    if (j + 1 == ig) b1 = 0;
                }
                float e0 = ex2(acc[mt][nt][hf * 2 + 0]);
                float e1 = ex2(acc[mt][nt][hf * 2 + 1]);
                if (b0 & 1) { p += e0; c++; }
                if (b0 & 2) { n += e0; }
                if (b1 & 1) { p += e1; c++; }
                if (b1 & 2) { n += e1; }
            }
            pos[rr] = p; neg[rr] = n; cnt[rr] = c;
        }
    }
}

// ---------------------------------------------------------------------------
// Kernel 2: HMMA GEMM (A pre-scaled) + lean predicated epilogue.
// Masks: coalesced LDG -> byte-pack -> double-buffered smem -> LDS.16.
// (R14 structure: burst convert before the MMA phase — best measured.)
// ---------------------------------------------------------------------------
extern __shared__ char dsm[];

__global__ __launch_bounds__(NT, 2) void hmma_main(
    const int* __restrict__ pmask, const int* __restrict__ nmask) {
    const uint32_t sb = smem_u32(dsm);
    const int tid = threadIdx.x, lid = tid & 31, wid = tid >> 5;
    const int wm = wid >> 2, wn = wid & 3;
    const int i0 = blockIdx.x * TI;
    const int split = blockIdx.y;
    const int jbase = split * JRANGE;

    // Prologue: A + B(0) via cp.async; masks(0) via LDG->pack->STS.
    fill_tile<TI>(sb + SM_A,  g_a + (size_t)i0 * DDIM, tid);
    fill_tile<TJ>(sb + SM_B0, g_b + (size_t)jbase * DDIM, tid);
    CP_COMMIT();
    {
        uint32_t mw0[8];
        mask_ldg_convert(mw0, pmask, nmask, i0, jbase, tid);
        mask_sts(sb + SM_M0, mw0, tid);
    }
    CP_WAIT0();
    __syncthreads();

    float pos[4] = {0, 0, 0, 0}, neg[4] = {0, 0, 0, 0};
    int cnt[4] = {0, 0, 0, 0};

    const int arow0 = wm * 32 + (lid & 15);
    const int asel  = lid >> 4;
    const int brow0 = wn * 32 + (lid & 7) + ((lid & 16) ? 8 : 0);
    const int bsel  = (lid >> 3) & 1;
    const int idiag = (i0 & ~127);
    const int jcol  = wn * 32 + (lid & 3) * 2;

    for (int t = 0; t < NSTEP; t++) {
        const int buf = t & 1;
        const uint32_t Bbase = sb + (buf ? SM_B1 : SM_B0);
        const uint32_t Mbase = sb + (buf ? SM_M1 : SM_M0);
        const int j0 = jbase + t * TJ;
        const bool have_next = (t + 1 < NSTEP);

        uint32_t mw[8];
        if (have_next) {
            fill_tile<TJ>(sb + (buf ? SM_B0 : SM_B1),
                          g_b + (size_t)(j0 + TJ) * DDIM, tid);
            CP_COMMIT();
            mask_ldg_convert(mw, pmask, nmask, i0, j0 + TJ, tid);
        }

        // --- MMA phase ---
        float acc[2][4][4];
        #pragma unroll
        for (int mt = 0; mt < 2; mt++)
            #pragma unroll
            for (int nt = 0; nt < 4; nt++)
                #pragma unroll
                for (int q = 0; q < 4; q++) acc[mt][nt][q] = 0.f;

        #pragma unroll
        for (int kk = 0; kk < 8; kk++) {
            uint32_t b[2][4];
            #pragma unroll
            for (int np = 0; np < 2; np++)
                ldmx4(Bbase + swz(brow0 + np * 16, 2 * kk + bsel),
                      b[np][0], b[np][1], b[np][2], b[np][3]);
            uint32_t a[2][4];
            #pragma unroll
            for (int mt = 0; mt < 2; mt++)
                ldmx4(sb + SM_A + swz(arow0 + mt * 16, 2 * kk + asel),
                      a[mt][0], a[mt][1], a[mt][2], a[mt][3]);
            #pragma unroll
            for (int np = 0; np < 2; np++)
                #pragma unroll
                for (int mt = 0; mt < 2; mt++) {
                    mma16816(acc[mt][2 * np],     a[mt], b[np][0], b[np][1]);
                    mma16816(acc[mt][2 * np + 1], a[mt], b[np][2], b[np][3]);
                }
        }

        // --- Epilogue (diag specialized out of the hot path) ---
        if (j0 == idiag)
            epilogue_step<true >(acc, Mbase, i0, j0, wm, lid, jcol, pos, neg, cnt);
        else
            epilogue_step<false>(acc, Mbase, i0, j0, wm, lid, jcol, pos, neg, cnt);

        if (have_next) {
            mask_sts(sb + (buf ? SM_M0 : SM_M1), mw, tid);
            CP_WAIT0();
        }
        __syncthreads();
    }

    // quad-lane reduce + store
    #pragma unroll
    for (int rr = 0; rr < 4; rr++) {
        float p = pos[rr], n = neg[rr], c = (float)cnt[rr];
        p += __shfl_xor_sync(0xffffffffu, p, 1);
        p += __shfl_xor_sync(0xffffffffu, p, 2);
        n += __shfl_xor_sync(0xffffffffu, n, 1);
        n += __shfl_xor_sync(0xffffffffu, n, 2);
        c += __shfl_xor_sync(0xffffffffu, c, 1);
        c += __shfl_xor_sync(0xffffffffu, c, 2);
        if ((lid & 3) == 0) {
            int mt = rr >> 1, hf = rr & 1;
            int ig = i0 + wm * 32 + mt * 16 + hf * 8 + (lid >> 2);
            int part = split * 4 + wn;
            g_pos[part * NR + ig] = p;
            g_neg[part * NR + ig] = n;
            g_cnt[part * NR + ig] = c;
        }
    }
}

// ---------------------------------------------------------------------------
// Kernel 3a: 64-block partial reduction of per-row log probs.
// ---------------------------------------------------------------------------
__global__ void final_a(void) {
    __shared__ float red[128];
    int r = blockIdx.x * 128 + threadIdx.x;
    float pos = 0.f, neg = 0.f, cnt = 0.f;
    #pragma unroll
    for (int p = 0; p < 8; p++) {
        pos += g_pos[p * NR + r];
        neg += g_neg[p * NR + r];
        cnt += g_cnt[p * NR + r];
    }
    red[threadIdx.x] = logf(pos / (pos + neg)) / cnt;
    __syncthreads();
    for (int s = 64; s > 0; s >>= 1) {
        if (threadIdx.x < s) red[threadIdx.x] += red[threadIdx.x + s];
        __syncthreads();
    }
    if (threadIdx.x == 0) g_partial[blockIdx.x] = red[0];
}
// Kernel 3b: combine 64 partials -> scalar.
__global__ void final_b(float* __restrict__ out) {
    int t = threadIdx.x;               // 64 threads
    float v = g_partial[t];
    #pragma unroll
    for (int o = 16; o > 0; o >>= 1) v += __shfl_xor_sync(0xffffffffu, v, o);
    __shared__ float w[2];
    if ((t & 31) == 0) w[t >> 5] = v;
    __syncthreads();
    if (t == 0) out[0] = -(w[0] + w[1]) / (float)NR;
}

// ---------------------------------------------------------------------------
extern "C" void kernel_launch(void* const* d_in, const int* in_sizes, int n_in,
                              void* d_out, int out_size) {
    const float* features = (const float*)d_in[0];
    const int*   pmask    = (const int*)d_in[1];
    const int*   nmask    = (const int*)d_in[2];
    float* out = (float*)d_out;

    cudaFuncSetAttribute(hmma_main,
                         cudaFuncAttributeMaxDynamicSharedMemorySize, SMEM_TOTAL);

    // Order [prepack, dummy, dummy, hmma, ...]: ncu slot lands on hmma_main.
    prepack_kernel<<<NR / 8, NT>>>(features);
    dummy_kernel<<<1, 32>>>();
    dummy_kernel<<<1, 32>>>();
    dim3 grid(NR / TI, JSPLIT);
    hmma_main<<<grid, NT, SMEM_TOTAL>>>(pmask, nmask);
    final_a<<<64, 128>>>();
    final_b<<<1, 64>>>(out);
}